// round 3
// baseline (speedup 1.0000x reference)
#include <cuda_runtime.h>

// AssociatorLoss on GB300 (sm_103a)
// kl = (1/B) * sum_{b,i,j,k,l} two * (ln(two) - ln(one))
//   one[b,i,j,k,l] = sum_m a[b,i,m,l] * a[b,j,k,m]
//   two[b,i,j,k,l] = sum_m a[b,i,j,m] * a[b,m,k,l]
// B = N = 32.
//
// One CTA per (b, i, k-block of 8): grid 4096, 256 threads, occ 2/SM.
// Shared memory (static, 41.5 KB):
//   sm_main[x][y][z] = a[b, x, kbase+y, z]
//   sm_i[y][z]       = a[b, i, y, z]
// Warp tile: lanes = kg(4) x lg(8); per-thread Tj=4, Tk=2, Tl=4.
// Accumulators packed as f32x2 pairs over l -> fma.rn.f32x2.
// Uniform operands (a[b,i,j,m], a[b,j,k,m]) read as scalar broadcast LDS.32
// (1 cyc each, writeback-model-optimal) instead of register vector caches,
// keeping regs ~95 so __launch_bounds__(256,2) holds without spills.

#define NN 32
#define KB 8
#define SPAD 36   // padded row stride in floats: 144 B, 16B-aligned

__device__ double g_sum;

union F4 {
    float4 v;
    float f[4];
    unsigned long long u[2];
};

__device__ __forceinline__ unsigned long long splat2(float x) {
    unsigned long long r;
    unsigned int xi = __float_as_uint(x);
    asm("mov.b64 %0, {%1, %1};" : "=l"(r) : "r"(xi));
    return r;
}

__device__ __forceinline__ void fma2(unsigned long long& d,
                                     unsigned long long a,
                                     unsigned long long b) {
    asm("fma.rn.f32x2 %0, %1, %2, %0;" : "+l"(d) : "l"(a), "l"(b));
}

__device__ __forceinline__ void unpack2(unsigned long long p, float& lo, float& hi) {
    unsigned int a, b;
    asm("mov.b64 {%0, %1}, %2;" : "=r"(a), "=r"(b) : "l"(p));
    lo = __uint_as_float(a);
    hi = __uint_as_float(b);
}

__global__ __launch_bounds__(256, 2)
void assoc_kernel(const float* __restrict__ a) {
    __shared__ __align__(16) float sm_main[NN][KB][SPAD];
    __shared__ __align__(16) float sm_i[NN][SPAD];
    __shared__ float sm_red[8];

    const int bid = blockIdx.x;
    const int kh  = bid & 3;           // k-block index (4 blocks of 8)
    const int i   = (bid >> 2) & 31;
    const int b   = bid >> 7;
    const int kbase = kh * KB;
    const float* __restrict__ ab = a + b * (NN * NN * NN);
    const int tid = threadIdx.x;

    // ---- Load phase (coalesced float4; rows 16B-aligned in smem) ----
    // sm_main: a[b, x, kbase+y, z]
    #pragma unroll
    for (int t = tid; t < 2048; t += 256) {
        int z4 = t & 7;
        int y  = (t >> 3) & 7;
        int x  = t >> 6;
        float4 v = *reinterpret_cast<const float4*>(ab + ((x * NN + kbase + y) * NN) + 4 * z4);
        *reinterpret_cast<float4*>(&sm_main[x][y][4 * z4]) = v;
    }
    // sm_i: a[b, i, y, z]
    {
        int z4 = tid & 7;
        int y  = tid >> 3;
        float4 v = *reinterpret_cast<const float4*>(ab + ((i * NN + y) * NN) + 4 * z4);
        *reinterpret_cast<float4*>(&sm_i[y][4 * z4]) = v;
    }
    __syncthreads();

    // ---- Thread tile decode ----
    const int w    = tid >> 5;
    const int lane = tid & 31;
    const int kg   = lane >> 3;       // 4 groups, Tk=2 -> local k = 2*kg + dk
    const int lg   = lane & 7;        // 8 groups, Tl=4 -> l = 4*lg + [0,4)
    const int jb   = w * 4;           // warp covers j in [4w, 4w+4)
    const int k0   = kg * 2;
    const int l0   = lg * 4;

    unsigned long long acc2[4][2][2];  // two[j, k, l-pair]
    unsigned long long acc1[4][2][2];  // one[j, k, l-pair]
    #pragma unroll
    for (int jj = 0; jj < 4; ++jj)
        #pragma unroll
        for (int dk = 0; dk < 2; ++dk)
            #pragma unroll
            for (int p = 0; p < 2; ++p) {
                acc2[jj][dk][p] = 0ull;
                acc1[jj][dk][p] = 0ull;
            }

    // ---- Main m-loop, fully unrolled ----
    #pragma unroll
    for (int m = 0; m < NN; ++m) {
        // Per-lane spread loads (128-bit):
        //   a2p[dk] = a[b, m, kbase+k0+dk, l0..l0+3]   (full 32-lane spread)
        //   A1p     = a[b, i, m, l0..l0+3]             (4-way kg redundancy)
        F4 a2p0, a2p1, A1p;
        a2p0.v = *reinterpret_cast<const float4*>(&sm_main[m][k0 + 0][l0]);
        a2p1.v = *reinterpret_cast<const float4*>(&sm_main[m][k0 + 1][l0]);
        A1p.v  = *reinterpret_cast<const float4*>(&sm_i[m][l0]);
        #pragma unroll
        for (int jj = 0; jj < 4; ++jj) {
            // two: += a[b,i,j,m] * a[b,m,k,l]   (warp-uniform scalar broadcast)
            unsigned long long ws = splat2(sm_i[jb + jj][m]);
            fma2(acc2[jj][0][0], ws, a2p0.u[0]);
            fma2(acc2[jj][0][1], ws, a2p0.u[1]);
            fma2(acc2[jj][1][0], ws, a2p1.u[0]);
            fma2(acc2[jj][1][1], ws, a2p1.u[1]);
            // one: += a[b,j,k,m] * a[b,i,m,l]   (4-distinct scalar, conflict-free)
            unsigned long long q0 = splat2(sm_main[jb + jj][k0 + 0][m]);
            fma2(acc1[jj][0][0], q0, A1p.u[0]);
            fma2(acc1[jj][0][1], q0, A1p.u[1]);
            unsigned long long q1 = splat2(sm_main[jb + jj][k0 + 1][m]);
            fma2(acc1[jj][1][0], q1, A1p.u[0]);
            fma2(acc1[jj][1][1], q1, A1p.u[1]);
        }
    }

    // ---- Epilogue: sum two * (lg2(two) - lg2(one)); ln2 scale applied at end ----
    float s = 0.0f;
    #pragma unroll
    for (int jj = 0; jj < 4; ++jj)
        #pragma unroll
        for (int dk = 0; dk < 2; ++dk)
            #pragma unroll
            for (int p = 0; p < 2; ++p) {
                float t0, t1, o0, o1;
                unpack2(acc2[jj][dk][p], t0, t1);
                unpack2(acc1[jj][dk][p], o0, o1);
                s += t0 * (__log2f(t0) - __log2f(o0));
                s += t1 * (__log2f(t1) - __log2f(o1));
            }

    // warp reduce -> smem -> one double atomic per CTA
    #pragma unroll
    for (int off = 16; off > 0; off >>= 1)
        s += __shfl_xor_sync(0xffffffffu, s, off);
    if (lane == 0) sm_red[w] = s;
    __syncthreads();
    if (tid == 0) {
        float tot = 0.0f;
        #pragma unroll
        for (int x = 0; x < 8; ++x) tot += sm_red[x];
        atomicAdd(&g_sum, (double)tot);
    }
}

__global__ void init_kernel() { g_sum = 0.0; }

__global__ void fin_kernel(float* __restrict__ out) {
    // base-2 logs -> natural log, divide by batch B=32
    out[0] = (float)(g_sum * 0.69314718055994530942 * (1.0 / 32.0));
}

extern "C" void kernel_launch(void* const* d_in, const int* in_sizes, int n_in,
                              void* d_out, int out_size) {
    (void)in_sizes; (void)n_in; (void)out_size;
    const float* a = (const float*)d_in[0];
    init_kernel<<<1, 1>>>();
    assoc_kernel<<<4096, 256>>>(a);
    fin_kernel<<<1, 1>>>((float*)d_out);
}

// round 5
// speedup vs baseline: 1.0863x; 1.0863x over previous
#include <cuda_runtime.h>

// AssociatorLoss on GB300 (sm_103a)
// kl = (1/B) * sum_{b,i,j,k,l} two * (ln(two) - ln(one))
//   one[b,i,j,k,l] = sum_m a[b,i,m,l] * a[b,j,k,m]
//   two[b,i,j,k,l] = sum_m a[b,i,j,m] * a[b,m,k,l]
// B = N = 32.
//
// Grid 4096 CTAs of 128 threads: CTA = (b, i-pair, j-half, k-block of 8).
// Occupancy 2 CTAs/SM (46.1 KB smem each) -> co-resident CTA hides the MUFU
// epilogue. Per-thread tile: Ti=2, Tj=4, Tk=2, Tl=4; 128 accumulator regs
// packed as f32x2 pairs over l (fma.rn.f32x2 = 2x fp32 FMA rate).
// Crossbar cost: 4 LDS.128 + 16 LDS.32 = 32 cyc per warp-m for 8 (i,j) combos
// (4 cyc/combo vs 6 in the 105us kernel) -> LDS 256 = FMA 256 cyc/m/SM.

#define NN 32
#define KB 8
#define SPAD 36   // padded row stride in floats: 144 B, 16B-aligned

__device__ double g_part[64];

union F4 {
    float4 v;
    float f[4];
    unsigned long long u[2];
};

__device__ __forceinline__ unsigned long long splat2(float x) {
    unsigned long long r;
    unsigned int xi = __float_as_uint(x);
    asm("mov.b64 %0, {%1, %1};" : "=l"(r) : "r"(xi));
    return r;
}

__device__ __forceinline__ void fma2(unsigned long long& d,
                                     unsigned long long a,
                                     unsigned long long b) {
    asm("fma.rn.f32x2 %0, %1, %2, %0;" : "+l"(d) : "l"(a), "l"(b));
}

__device__ __forceinline__ void unpack2(unsigned long long p, float& lo, float& hi) {
    unsigned int a, b;
    asm("mov.b64 {%0, %1}, %2;" : "=r"(a), "=r"(b) : "l"(p));
    lo = __uint_as_float(a);
    hi = __uint_as_float(b);
}

__global__ __launch_bounds__(128)
void assoc_kernel(const float* __restrict__ a) {
    __shared__ __align__(16) float sm_main[NN][KB][SPAD];   // a[b, x, kbase+y, z]
    __shared__ __align__(16) float sm_i[2][NN][SPAD];       // a[b, ibase+ii, y, z]
    __shared__ float sm_red[4];

    const int bid = blockIdx.x;
    const int kh  = bid & 3;            // k-block (4 blocks of 8)
    const int jh  = (bid >> 2) & 1;     // j-half (2 halves of 16)
    const int ip  = (bid >> 3) & 15;    // i-pair (16 pairs)
    const int b   = bid >> 7;
    const int kbase = kh * KB;
    const int ibase = ip * 2;
    const float* __restrict__ ab = a + b * (NN * NN * NN);
    const int tid = threadIdx.x;

    // ---- Load phase (coalesced float4; rows 16B-aligned in smem) ----
    #pragma unroll
    for (int t = tid; t < 2048; t += 128) {
        int z4 = t & 7;
        int y  = (t >> 3) & 7;
        int x  = t >> 6;
        float4 v = *reinterpret_cast<const float4*>(ab + ((x * NN + kbase + y) * NN) + 4 * z4);
        *reinterpret_cast<float4*>(&sm_main[x][y][4 * z4]) = v;
    }
    #pragma unroll
    for (int t = tid; t < 512; t += 128) {
        int z4 = t & 7;
        int y  = (t >> 3) & 31;
        int ii = t >> 8;
        float4 v = *reinterpret_cast<const float4*>(ab + ((ibase + ii) * NN + y) * NN + 4 * z4);
        *reinterpret_cast<float4*>(&sm_i[ii][y][4 * z4]) = v;
    }
    __syncthreads();

    // ---- Thread tile decode ----
    const int w    = tid >> 5;           // 4 warps
    const int lane = tid & 31;
    const int kg   = lane >> 3;          // 4 groups -> local k = 2*kg + dk
    const int lg   = lane & 7;           // 8 groups -> l = 4*lg + [0,4)
    const int jb   = jh * 16 + w * 4;    // warp covers j in [jb, jb+4)
    const int k0   = kg * 2;
    const int l0   = lg * 4;

    unsigned long long acc2[2][4][2][2];  // two[ii][jj][dk][pair]
    unsigned long long acc1[2][4][2][2];  // one[ii][jj][dk][pair]
    #pragma unroll
    for (int ii = 0; ii < 2; ++ii)
        #pragma unroll
        for (int jj = 0; jj < 4; ++jj)
            #pragma unroll
            for (int dk = 0; dk < 2; ++dk)
                #pragma unroll
                for (int p = 0; p < 2; ++p) {
                    acc2[ii][jj][dk][p] = 0ull;
                    acc1[ii][jj][dk][p] = 0ull;
                }

    // ---- Main m-loop (unroll 2 x 4m blocks: body ~25KB, fits I$ L1.5) ----
    #pragma unroll 2
    for (int mq = 0; mq < 8; ++mq) {
        #pragma unroll
        for (int mm = 0; mm < 4; ++mm) {
            const int m = 4 * mq + mm;
            // spread vectors (shared across ii, jj):
            F4 a2p0, a2p1, A1p0, A1p1;
            a2p0.v = *reinterpret_cast<const float4*>(&sm_main[m][k0 + 0][l0]); // a[b,m,k,l]
            a2p1.v = *reinterpret_cast<const float4*>(&sm_main[m][k0 + 1][l0]);
            A1p0.v = *reinterpret_cast<const float4*>(&sm_i[0][m][l0]);          // a[b,i,m,l]
            A1p1.v = *reinterpret_cast<const float4*>(&sm_i[1][m][l0]);
            #pragma unroll
            for (int jj = 0; jj < 4; ++jj) {
                // one-operand scalars, shared across ii (4-distinct LDS, 1 phase)
                unsigned long long q0 = splat2(sm_main[jb + jj][k0 + 0][m]);     // a[b,j,k,m]
                unsigned long long q1 = splat2(sm_main[jb + jj][k0 + 1][m]);
                // two-operand scalars per ii (warp-uniform broadcast LDS)
                unsigned long long ws0 = splat2(sm_i[0][jb + jj][m]);            // a[b,i,j,m]
                unsigned long long ws1 = splat2(sm_i[1][jb + jj][m]);

                fma2(acc2[0][jj][0][0], ws0, a2p0.u[0]);
                fma2(acc2[0][jj][0][1], ws0, a2p0.u[1]);
                fma2(acc2[0][jj][1][0], ws0, a2p1.u[0]);
                fma2(acc2[0][jj][1][1], ws0, a2p1.u[1]);
                fma2(acc2[1][jj][0][0], ws1, a2p0.u[0]);
                fma2(acc2[1][jj][0][1], ws1, a2p0.u[1]);
                fma2(acc2[1][jj][1][0], ws1, a2p1.u[0]);
                fma2(acc2[1][jj][1][1], ws1, a2p1.u[1]);

                fma2(acc1[0][jj][0][0], q0, A1p0.u[0]);
                fma2(acc1[0][jj][0][1], q0, A1p0.u[1]);
                fma2(acc1[0][jj][1][0], q1, A1p0.u[0]);
                fma2(acc1[0][jj][1][1], q1, A1p0.u[1]);
                fma2(acc1[1][jj][0][0], q0, A1p1.u[0]);
                fma2(acc1[1][jj][0][1], q0, A1p1.u[1]);
                fma2(acc1[1][jj][1][0], q1, A1p1.u[0]);
                fma2(acc1[1][jj][1][1], q1, A1p1.u[1]);
            }
        }
    }

    // ---- Epilogue: sum two * (lg2(two) - lg2(one)); ln2 scale at the end ----
    float s = 0.0f;
    #pragma unroll
    for (int ii = 0; ii < 2; ++ii)
        #pragma unroll
        for (int jj = 0; jj < 4; ++jj)
            #pragma unroll
            for (int dk = 0; dk < 2; ++dk)
                #pragma unroll
                for (int p = 0; p < 2; ++p) {
                    float t0, t1, o0, o1;
                    unpack2(acc2[ii][jj][dk][p], t0, t1);
                    unpack2(acc1[ii][jj][dk][p], o0, o1);
                    s += t0 * (__log2f(t0) - __log2f(o0));
                    s += t1 * (__log2f(t1) - __log2f(o1));
                }

    // warp reduce -> smem -> one double atomic per CTA (64-way spread slots)
    #pragma unroll
    for (int off = 16; off > 0; off >>= 1)
        s += __shfl_xor_sync(0xffffffffu, s, off);
    if (lane == 0) sm_red[w] = s;
    __syncthreads();
    if (tid == 0) {
        float tot = sm_red[0] + sm_red[1] + sm_red[2] + sm_red[3];
        atomicAdd(&g_part[bid & 63], (double)tot);
    }
}

__global__ void init_kernel() {
    if (threadIdx.x < 64) g_part[threadIdx.x] = 0.0;
}

__global__ void fin_kernel(float* __restrict__ out) {
    double tot = 0.0;
    #pragma unroll
    for (int x = 0; x < 64; ++x) tot += g_part[x];
    // base-2 logs -> natural log, divide by batch B=32
    out[0] = (float)(tot * 0.69314718055994530942 * (1.0 / 32.0));
}

extern "C" void kernel_launch(void* const* d_in, const int* in_sizes, int n_in,
                              void* d_out, int out_size) {
    (void)in_sizes; (void)n_in; (void)out_size;
    const float* a = (const float*)d_in[0];
    init_kernel<<<1, 64>>>();
    assoc_kernel<<<4096, 128>>>(a);
    fin_kernel<<<1, 1>>>((float*)d_out);
}